// round 11
// baseline (speedup 1.0000x reference)
#include <cuda_runtime.h>

// Problem constants (fixed by dataset: B=2, N=512, E=128, H=8, D=16)
#define B_    2
#define N_    512
#define E_    128
#define H_    8
#define D_    16
#define ROWS_ (B_ * N_)   // 1024

// Scratch (device globals: allocation-free rule)
__device__ float g_q[ROWS_ * E_];    // q * 0.25 (1/sqrt(D))
__device__ float g_v[ROWS_ * E_];

// ---------------- packed fp32x2 helpers (Blackwell FFMA2/FADD2) -------------
typedef unsigned long long u64;
#define ABS2_MASK 0x7fffffff7fffffffULL

__device__ __forceinline__ u64 pack2(float lo, float hi) {
    u64 r; asm("mov.b64 %0, {%1, %2};" : "=l"(r) : "f"(lo), "f"(hi)); return r;
}
__device__ __forceinline__ float2 unpk2(u64 v) {
    float2 f; asm("mov.b64 {%0, %1}, %2;" : "=f"(f.x), "=f"(f.y) : "l"(v)); return f;
}
__device__ __forceinline__ u64 ffma2(u64 a, u64 b, u64 c) {
    u64 d; asm("fma.rn.f32x2 %0, %1, %2, %3;" : "=l"(d) : "l"(a), "l"(b), "l"(c)); return d;
}
__device__ __forceinline__ u64 fadd2(u64 a, u64 b) {
    u64 d; asm("add.rn.f32x2 %0, %1, %2;" : "=l"(d) : "l"(a), "l"(b)); return d;
}

// Butterfly transpose-reduce over 16 per-lane partials: returns, on lane L,
// the full 32-lane sum of pc[bitrev4(L & 15)].
__device__ __forceinline__ float butterfly16(float* pc, int lane) {
    #pragma unroll
    for (int r = 0; r < 4; r++) {
        const int half = 8 >> r;
        const bool hi = (lane >> r) & 1;
        #pragma unroll
        for (int j = 0; j < 8; j++) {
            if (j < half) {
                float send = hi ? pc[j] : pc[j + half];
                float keep = hi ? pc[j + half] : pc[j];
                float recv = __shfl_xor_sync(0xffffffffu, send, 1 << r);
                pc[j] = keep + recv;
            }
        }
    }
    return pc[0] + __shfl_xor_sync(0xffffffffu, pc[0], 16);
}
__device__ __forceinline__ int bitrev4(int l) {
    return ((l & 1) << 3) | (((l >> 1) & 1) << 2)
         | (((l >> 2) & 1) << 1) | ((l >> 3) & 1);
}

// ---------------------------------------------------------------------------
// qv GEMV: one CTA per row, warp = head. No smem, no syncs; w_qkv slices stay
// L1-resident across the ~7 CTAs each SM processes.
// ---------------------------------------------------------------------------
__global__ __launch_bounds__(256) void qv_kernel(const float* __restrict__ x,
                                                 const float* __restrict__ w_qkv) {
    const int row  = blockIdx.x;
    const int tid  = threadIdx.x;
    const int lane = tid & 31;
    const int h    = tid >> 5;

    float4 x4 = ((const float4*)(x + row * 128))[lane];
    float pc[16];
    #pragma unroll
    for (int i = 0; i < 16; i++) {
        const float4 wq = *(const float4*)&w_qkv[(h * 16 + i) * 128 + lane * 4];
        pc[i] = fmaf(x4.x, wq.x, fmaf(x4.y, wq.y, fmaf(x4.z, wq.z, x4.w * wq.w)));
    }
    float qv = butterfly16(pc, lane);
    if (lane < 16) g_q[row * 128 + h * 16 + bitrev4(lane)] = 0.25f * qv;

    #pragma unroll
    for (int i = 0; i < 16; i++) {
        const float4 wv = *(const float4*)&w_qkv[(256 + h * 16 + i) * 128 + lane * 4];
        pc[i] = fmaf(x4.x, wv.x, fmaf(x4.y, wv.y, fmaf(x4.z, wv.z, x4.w * wv.w)));
    }
    float vv = butterfly16(pc, lane);
    if (lane < 16) g_v[row * 128 + h * 16 + bitrev4(lane)] = vv;
}

// ---------------------------------------------------------------------------
// Fused attention + projection — R5 engine with p values moved to smem
// (p_s[8][512]) to cut live registers and allow 4 CTAs/SM.
//   lrelu(em*w+b) = 0.505(em*w+b) + 0.495|w||em + b/w|
//   phase1: s = c0 + c1*em + sum_d g_d|em + r_d|  (running max kept inline)
//   phase2: acc_d = sum_m p|em + rv_d|; hat via S1/Z linear fold.
// ---------------------------------------------------------------------------
__global__ __launch_bounds__(256, 4) void attn_proj_kernel(const float* __restrict__ e,
                                                           const float* __restrict__ w_ekv,
                                                           const float* __restrict__ b_ekv,
                                                           const float* __restrict__ w_prj,
                                                           const float* __restrict__ b_prj,
                                                           float* __restrict__ out) {
    __shared__ float e_s[N_];
    __shared__ float q_s[128], v_s[128];
    __shared__ float wk_s[128], bk_s[128], wv_s[128], bv_s[128];
    __shared__ float p_s[H_][N_];     // per-head scores/probs (16 KB)
    __shared__ float hat_s[128];

    const int row  = blockIdx.x;     // b*N + n
    const int tid  = threadIdx.x;
    const int lane = tid & 31;
    const int h    = tid >> 5;       // warp == head

    if (tid < 128)
        ((float4*)e_s)[tid] = ((const float4*)(e + row * N_))[tid];
    if (tid < 128) {
        q_s[tid]  = g_q[row * 128 + tid];
        v_s[tid]  = g_v[row * 128 + tid];
        wk_s[tid] = w_ekv[tid];
        bk_s[tid] = b_ekv[tid];
    } else {
        int t = tid - 128;
        wv_s[t] = w_ekv[128 + t];
        bv_s[t] = b_ekv[128 + t];
    }
    __syncthreads();

    // ======== phase 1: scores -> p_s, running max ========
    float mx = -1e30f;
    {
        u64 r2[8], g2[8];
        float c0 = 0.f, c1 = 0.f;
        #pragma unroll
        for (int dd = 0; dd < 8; dd++) {
            float2 w = ((const float2*)wk_s)[h * 8 + dd];
            float2 b = ((const float2*)bk_s)[h * 8 + dd];
            float2 q = ((const float2*)q_s)[h * 8 + dd];
            r2[dd] = pack2(__fdividef(b.x, w.x), __fdividef(b.y, w.y));
            g2[dd] = pack2(0.495f * q.x * fabsf(w.x), 0.495f * q.y * fabsf(w.y));
            c1 = fmaf(q.x, w.x, fmaf(q.y, w.y, c1));
            c0 = fmaf(q.x, b.x, fmaf(q.y, b.y, c0));
        }
        c1 *= 0.505f; c0 *= 0.505f;

        #pragma unroll
        for (int i = 0; i < 16; i++) {
            const float em = e_s[i * 32 + lane];
            const u64 em2 = pack2(em, em);
            u64 acc2 = 0ULL;
            #pragma unroll
            for (int dd = 0; dd < 8; dd++) {
                u64 u2 = fadd2(em2, r2[dd]);
                acc2 = ffma2(g2[dd], u2 & ABS2_MASK, acc2);
            }
            float2 f = unpk2(acc2);
            float sc = fmaf(c1, em, c0) + f.x + f.y;
            mx = fmaxf(mx, sc);
            p_s[h][i * 32 + lane] = sc;
        }
    }
    #pragma unroll
    for (int k = 16; k >= 1; k >>= 1) mx = fmaxf(mx, __shfl_xor_sync(0xffffffffu, mx, k));

    // ======== exp pass: p_s <- exp(s - mx); Z, S1 ========
    float Z = 0.f, S1 = 0.f;
    #pragma unroll
    for (int i = 0; i < 16; i++) {
        float p = __expf(p_s[h][i * 32 + lane] - mx);
        p_s[h][i * 32 + lane] = p;
        Z += p;
        S1 = fmaf(p, e_s[i * 32 + lane], S1);
    }
    #pragma unroll
    for (int k = 16; k >= 1; k >>= 1) {
        Z  += __shfl_xor_sync(0xffffffffu, Z, k);
        S1 += __shfl_xor_sync(0xffffffffu, S1, k);
    }
    const float invZ = 1.f / Z;

    // ======== phase 2: acc_d = sum_m p |em + bv_d/wv_d| ========
    float acc[16];
    {
        u64 rv2[8], acc2[8];
        #pragma unroll
        for (int dd = 0; dd < 8; dd++) {
            float2 w = ((const float2*)wv_s)[h * 8 + dd];
            float2 b = ((const float2*)bv_s)[h * 8 + dd];
            rv2[dd] = pack2(__fdividef(b.x, w.x), __fdividef(b.y, w.y));
            acc2[dd] = 0ULL;
        }
        #pragma unroll
        for (int i = 0; i < 16; i++) {
            const float em = e_s[i * 32 + lane];
            const float p  = p_s[h][i * 32 + lane];
            const u64 em2 = pack2(em, em);
            const u64 p2  = pack2(p, p);
            #pragma unroll
            for (int dd = 0; dd < 8; dd++) {
                u64 u2 = fadd2(em2, rv2[dd]);
                acc2[dd] = ffma2(p2, u2 & ABS2_MASK, acc2[dd]);
            }
        }
        #pragma unroll
        for (int dd = 0; dd < 8; dd++) {
            float2 fb = unpk2(acc2[dd]);
            acc[2 * dd]     = fb.x;
            acc[2 * dd + 1] = fb.y;
        }
    }

    // ---- butterfly transpose-reduce + epilogue hat ----
    float tot = butterfly16(acc, lane);
    if (lane < 16) {
        int d = bitrev4(lane);
        float wvd = wv_s[h * 16 + d], bvd = bv_s[h * 16 + d];
        float lin = 0.505f * fmaf(wvd, S1, bvd * Z);
        hat_s[h * 16 + d] = v_s[h * 16 + d]
                          + fmaf(0.495f * fabsf(wvd), tot, lin) * invZ;
    }
    __syncthreads();

    // ======== projection: warp h -> cols [h*16, h*16+16) ========
    {
        float4 h4 = ((const float4*)hat_s)[lane];
        float pc[16];
        #pragma unroll
        for (int i = 0; i < 16; i++) {
            const int c = h * 16 + i;
            float4 wv = *(const float4*)&w_prj[c * 128 + lane * 4];
            pc[i] = fmaf(h4.x, wv.x, fmaf(h4.y, wv.y, fmaf(h4.z, wv.z, h4.w * wv.w)));
        }
        float cval = butterfly16(pc, lane);
        if (lane < 16) {
            const int c = h * 16 + bitrev4(lane);
            out[row * 128 + c] = cval + b_prj[c];
        }
    }
}

// ---------------------------------------------------------------------------
extern "C" void kernel_launch(void* const* d_in, const int* in_sizes, int n_in,
                              void* d_out, int out_size) {
    const float* x     = (const float*)d_in[0];
    const float* e     = (const float*)d_in[1];
    const float* w_qkv = (const float*)d_in[2];
    const float* w_ekv = (const float*)d_in[3];
    const float* b_ekv = (const float*)d_in[4];
    const float* w_prj = (const float*)d_in[5];
    const float* b_prj = (const float*)d_in[6];
    float* out = (float*)d_out;

    qv_kernel       <<<ROWS_, 256>>>(x, w_qkv);
    attn_proj_kernel<<<ROWS_, 256>>>(e, w_ekv, b_ekv, w_prj, b_prj, out);
}

// round 12
// speedup vs baseline: 1.2000x; 1.2000x over previous
#include <cuda_runtime.h>

// Problem constants (fixed by dataset: B=2, N=512, E=128, H=8, D=16)
#define B_    2
#define N_    512
#define E_    128
#define H_    8
#define D_    16
#define ROWS_ (B_ * N_)   // 1024

// Scratch (device globals: allocation-free rule)
__device__ float g_q[ROWS_ * E_];    // q * 0.25 (1/sqrt(D))
__device__ float g_v[ROWS_ * E_];

// ---------------- packed fp32x2 helpers (Blackwell FFMA2/FADD2) -------------
typedef unsigned long long u64;
#define ABS2_MASK 0x7fffffff7fffffffULL

__device__ __forceinline__ u64 pack2(float lo, float hi) {
    u64 r; asm("mov.b64 %0, {%1, %2};" : "=l"(r) : "f"(lo), "f"(hi)); return r;
}
__device__ __forceinline__ float2 unpk2(u64 v) {
    float2 f; asm("mov.b64 {%0, %1}, %2;" : "=f"(f.x), "=f"(f.y) : "l"(v)); return f;
}
__device__ __forceinline__ u64 ffma2(u64 a, u64 b, u64 c) {
    u64 d; asm("fma.rn.f32x2 %0, %1, %2, %3;" : "=l"(d) : "l"(a), "l"(b), "l"(c)); return d;
}
__device__ __forceinline__ u64 fadd2(u64 a, u64 b) {
    u64 d; asm("add.rn.f32x2 %0, %1, %2;" : "=l"(d) : "l"(a), "l"(b)); return d;
}

// ---------------------------------------------------------------------------
// qv GEMM: C[32r x 64c] = X[32 x 128] @ W[64 x 128]^T per CTA.
// R5 tiling (3.7us measured), inner loop converted to FFMA2 (c-dim packed):
// fma-pipe work halves (16 FFMA -> 8 FFMA2 per (jb,k)); packs go to alu pipe.
// ---------------------------------------------------------------------------
#define QV_SMEM_BYTES (32 * 128 * 4 + 128 * 68 * 4)

__global__ __launch_bounds__(128) void qv_kernel(const float* __restrict__ x,
                                                 const float* __restrict__ w_qkv) {
    extern __shared__ float sm[];
    float (*x_s)[128] = (float(*)[128])sm;
    float (*w_s)[68]  = (float(*)[68])(sm + 32 * 128);

    const int tid  = threadIdx.x;
    const int row0 = blockIdx.y * 32;
    const int st   = blockIdx.x;                           // 0,1 -> q ; 2,3 -> v
    const int wbase = (st < 2) ? st * 64 : 128 + st * 64;  // 0,64,256,320
    const float* w_rows = w_qkv + wbase * 128;

    {
        const float4* x4 = (const float4*)(x + row0 * 128);
        float4* xs4 = (float4*)x_s;
        #pragma unroll
        for (int i = 0; i < 8; i++) xs4[tid + i * 128] = x4[tid + i * 128];
    }
    #pragma unroll
    for (int i = 0; i < 64; i++) {
        int idx = tid + i * 128;
        int j = idx & 127, c = idx >> 7;
        w_s[j][c] = w_rows[c * 128 + j];
    }
    __syncthreads();

    const int tx = tid & 15;
    const int ty = tid >> 4;
    u64 acc2[4][2];
    #pragma unroll
    for (int r = 0; r < 4; r++) { acc2[r][0] = 0ULL; acc2[r][1] = 0ULL; }

    #pragma unroll 4
    for (int jb = 0; jb < 32; jb++) {
        float4 xr[4], wv[4];
        #pragma unroll
        for (int r = 0; r < 4; r++) xr[r] = *(const float4*)&x_s[ty * 4 + r][jb * 4];
        #pragma unroll
        for (int k = 0; k < 4; k++) wv[k] = *(const float4*)&w_s[jb * 4 + k][tx * 4];
        #pragma unroll
        for (int k = 0; k < 4; k++) {
            const u64 w01 = pack2(wv[k].x, wv[k].y);
            const u64 w23 = pack2(wv[k].z, wv[k].w);
            #pragma unroll
            for (int r = 0; r < 4; r++) {
                float xs = (k == 0) ? xr[r].x : (k == 1) ? xr[r].y
                         : (k == 2) ? xr[r].z : xr[r].w;
                const u64 x2 = pack2(xs, xs);
                acc2[r][0] = ffma2(x2, w01, acc2[r][0]);
                acc2[r][1] = ffma2(x2, w23, acc2[r][1]);
            }
        }
    }

    const float scale = (st < 2) ? 0.25f : 1.0f;
    float* dst = (st < 2) ? g_q : g_v;
    const int cg = (st & 1) * 64 + tx * 4;
    #pragma unroll
    for (int r = 0; r < 4; r++) {
        float2 a01 = unpk2(acc2[r][0]);
        float2 a23 = unpk2(acc2[r][1]);
        float4 o = {a01.x * scale, a01.y * scale, a23.x * scale, a23.y * scale};
        *(float4*)&dst[(row0 + ty * 4 + r) * 128 + cg] = o;
    }

#if __CUDA_ARCH__ >= 900
    cudaTriggerProgrammaticLaunchCompletion();
#endif
}

// ---------------------------------------------------------------------------
// Fused attention + projection — EXACT Round-5 engine (22.0us measured).
// Only change: independent staging first, then cudaGridDependencySynchronize()
// (PDL) before reading g_q/g_v produced by qv_kernel.
// ---------------------------------------------------------------------------
__global__ __launch_bounds__(256, 3) void attn_proj_kernel(const float* __restrict__ e,
                                                           const float* __restrict__ w_ekv,
                                                           const float* __restrict__ b_ekv,
                                                           const float* __restrict__ w_prj,
                                                           const float* __restrict__ b_prj,
                                                           float* __restrict__ out) {
    __shared__ float e_s[N_];
    __shared__ float q_s[128], v_s[128];
    __shared__ float wk_s[128], bk_s[128], wv_s[128], bv_s[128];
    __shared__ float hat_s[128];

    const int row  = blockIdx.x;     // b*N + n
    const int tid  = threadIdx.x;
    const int lane = tid & 31;
    const int h    = tid >> 5;       // warp == head

    // ---- independent staging (overlaps primary grid under PDL) ----
    if (tid < 128)
        ((float4*)e_s)[tid] = ((const float4*)(e + row * N_))[tid];
    if (tid < 128) {
        wk_s[tid] = w_ekv[tid];
        bk_s[tid] = b_ekv[tid];
    } else {
        int t = tid - 128;
        wv_s[t] = w_ekv[128 + t];
        bv_s[t] = b_ekv[128 + t];
    }

#if __CUDA_ARCH__ >= 900
    cudaGridDependencySynchronize();   // wait for qv_kernel's g_q/g_v
#endif
    if (tid < 128) {
        q_s[tid] = g_q[row * 128 + tid];
        v_s[tid] = g_v[row * 128 + tid];
    }
    __syncthreads();

    float s[16];

    // ======== phase 1: scores (EXACT R5) ========
    {
        u64 r2[8], g2[8];
        float c0 = 0.f, c1 = 0.f;
        #pragma unroll
        for (int dd = 0; dd < 8; dd++) {
            float2 w = ((const float2*)wk_s)[h * 8 + dd];
            float2 b = ((const float2*)bk_s)[h * 8 + dd];
            float2 q = ((const float2*)q_s)[h * 8 + dd];
            r2[dd] = pack2(__fdividef(b.x, w.x), __fdividef(b.y, w.y));
            g2[dd] = pack2(0.495f * q.x * fabsf(w.x), 0.495f * q.y * fabsf(w.y));
            c1 = fmaf(q.x, w.x, fmaf(q.y, w.y, c1));
            c0 = fmaf(q.x, b.x, fmaf(q.y, b.y, c0));
        }
        c1 *= 0.505f; c0 *= 0.505f;

        #pragma unroll
        for (int i = 0; i < 16; i++) {
            const float em = e_s[i * 32 + lane];
            const u64 em2 = pack2(em, em);
            u64 acc2 = 0ULL;
            #pragma unroll
            for (int dd = 0; dd < 8; dd++) {
                u64 u2 = fadd2(em2, r2[dd]);
                acc2 = ffma2(g2[dd], u2 & ABS2_MASK, acc2);
            }
            float2 f = unpk2(acc2);
            s[i] = fmaf(c1, em, c0) + f.x + f.y;
        }
    }

    // ======== softmax over m (+ S1 = sum p*em) — EXACT R5 ========
    float mx = s[0];
    #pragma unroll
    for (int i = 1; i < 16; i++) mx = fmaxf(mx, s[i]);
    #pragma unroll
    for (int k = 16; k >= 1; k >>= 1) mx = fmaxf(mx, __shfl_xor_sync(0xffffffffu, mx, k));
    float Z = 0.f, S1 = 0.f;
    #pragma unroll
    for (int i = 0; i < 16; i++) {
        s[i] = __expf(s[i] - mx);
        Z += s[i];
        S1 = fmaf(s[i], e_s[i * 32 + lane], S1);
    }
    #pragma unroll
    for (int k = 16; k >= 1; k >>= 1) {
        Z  += __shfl_xor_sync(0xffffffffu, Z, k);
        S1 += __shfl_xor_sync(0xffffffffu, S1, k);
    }
    const float invZ = 1.f / Z;

    // ======== phase 2: acc_d = sum_m p |em + bv_d/wv_d| — EXACT R5 ========
    float acc[16];
    {
        u64 rv2[8], acc2[8];
        #pragma unroll
        for (int dd = 0; dd < 8; dd++) {
            float2 w = ((const float2*)wv_s)[h * 8 + dd];
            float2 b = ((const float2*)bv_s)[h * 8 + dd];
            rv2[dd] = pack2(__fdividef(b.x, w.x), __fdividef(b.y, w.y));
            acc2[dd] = 0ULL;
        }
        #pragma unroll
        for (int i = 0; i < 16; i++) {
            const float em = e_s[i * 32 + lane];
            const u64 em2 = pack2(em, em);
            const u64 p2  = pack2(s[i], s[i]);
            #pragma unroll
            for (int dd = 0; dd < 8; dd++) {
                u64 u2 = fadd2(em2, rv2[dd]);
                acc2[dd] = ffma2(p2, u2 & ABS2_MASK, acc2[dd]);
            }
        }
        #pragma unroll
        for (int dd = 0; dd < 8; dd++) {
            float2 fb = unpk2(acc2[dd]);
            acc[2 * dd]     = fb.x;
            acc[2 * dd + 1] = fb.y;
        }
    }

    // ---- butterfly transpose-reduce: lane L ends with d = bitrev4(L&15) ----
    #pragma unroll
    for (int r = 0; r < 4; r++) {
        const int half = 8 >> r;
        const bool hi = (lane >> r) & 1;
        #pragma unroll
        for (int j = 0; j < 8; j++) {
            if (j < half) {
                float send = hi ? acc[j] : acc[j + half];
                float keep = hi ? acc[j + half] : acc[j];
                float recv = __shfl_xor_sync(0xffffffffu, send, 1 << r);
                acc[j] = keep + recv;
            }
        }
    }
    float tot = acc[0] + __shfl_xor_sync(0xffffffffu, acc[0], 16);
    if (lane < 16) {
        int d = ((lane & 1) << 3) | (((lane >> 1) & 1) << 2)
              | (((lane >> 2) & 1) << 1) | ((lane >> 3) & 1);
        float wvd = wv_s[h * 16 + d], bvd = bv_s[h * 16 + d];
        float lin = 0.505f * fmaf(wvd, S1, bvd * Z);
        hat_s[h * 16 + d] = v_s[h * 16 + d]
                          + fmaf(0.495f * fabsf(wvd), tot, lin) * invZ;
    }
    __syncthreads();

    // ======== fused projection: warp h -> cols [h*16, h*16+16) ========
    {
        float4 h4 = ((const float4*)hat_s)[lane];
        float pc[16];
        #pragma unroll
        for (int i = 0; i < 16; i++) {
            const int c = h * 16 + i;
            float4 wv = *(const float4*)&w_prj[c * 128 + lane * 4];
            pc[i] = fmaf(h4.x, wv.x, fmaf(h4.y, wv.y, fmaf(h4.z, wv.z, h4.w * wv.w)));
        }
        #pragma unroll
        for (int r = 0; r < 4; r++) {
            const int half = 8 >> r;
            const bool hi = (lane >> r) & 1;
            #pragma unroll
            for (int j = 0; j < 8; j++) {
                if (j < half) {
                    float send = hi ? pc[j] : pc[j + half];
                    float keep = hi ? pc[j + half] : pc[j];
                    float recv = __shfl_xor_sync(0xffffffffu, send, 1 << r);
                    pc[j] = keep + recv;
                }
            }
        }
        float cval = pc[0] + __shfl_xor_sync(0xffffffffu, pc[0], 16);
        if (lane < 16) {
            int i = ((lane & 1) << 3) | (((lane >> 1) & 1) << 2)
                  | (((lane >> 2) & 1) << 1) | ((lane >> 3) & 1);
            const int c = h * 16 + i;
            out[row * 128 + c] = cval + b_prj[c];
        }
    }
}

// ---------------------------------------------------------------------------
extern "C" void kernel_launch(void* const* d_in, const int* in_sizes, int n_in,
                              void* d_out, int out_size) {
    const float* x     = (const float*)d_in[0];
    const float* e     = (const float*)d_in[1];
    const float* w_qkv = (const float*)d_in[2];
    const float* w_ekv = (const float*)d_in[3];
    const float* b_ekv = (const float*)d_in[4];
    const float* w_prj = (const float*)d_in[5];
    const float* b_prj = (const float*)d_in[6];
    float* out = (float*)d_out;

    cudaFuncSetAttribute((const void*)qv_kernel,
                         cudaFuncAttributeMaxDynamicSharedMemorySize, QV_SMEM_BYTES);

    qv_kernel<<<dim3(4, 32), 128, QV_SMEM_BYTES>>>(x, w_qkv);

    // PDL launch of the dependent kernel; fall back to plain launch if the
    // attribute is rejected on this driver/toolkit.
    cudaLaunchConfig_t cfg = {};
    cfg.gridDim  = dim3(ROWS_);
    cfg.blockDim = dim3(256);
    cfg.dynamicSmemBytes = 0;
    cudaLaunchAttribute attrs[1];
    attrs[0].id = cudaLaunchAttributeProgrammaticStreamSerialization;
    attrs[0].val.programmaticStreamSerializationAllowed = 1;
    cfg.attrs = attrs;
    cfg.numAttrs = 1;
    cudaError_t err = cudaLaunchKernelEx(&cfg, attn_proj_kernel,
                                         e, w_ekv, b_ekv, w_prj, b_prj, out);
    if (err != cudaSuccess) {
        attn_proj_kernel<<<ROWS_, 256>>>(e, w_ekv, b_ekv, w_prj, b_prj, out);
    }
}

// round 13
// speedup vs baseline: 1.4250x; 1.1875x over previous
#include <cuda_runtime.h>

// Problem constants (fixed by dataset: B=2, N=512, E=128, H=8, D=16)
#define B_    2
#define N_    512
#define E_    128
#define H_    8
#define D_    16
#define ROWS_ (B_ * N_)   // 1024

// Scratch (device globals: allocation-free rule)
__device__ float g_q[ROWS_ * E_];    // q * 0.25 (1/sqrt(D))
__device__ float g_v[ROWS_ * E_];

// ---------------- packed fp32x2 helpers (Blackwell FFMA2/FADD2) -------------
typedef unsigned long long u64;
#define ABS2_MASK 0x7fffffff7fffffffULL
#define FULLM 0xffffffffu

__device__ __forceinline__ u64 pack2(float lo, float hi) {
    u64 r; asm("mov.b64 %0, {%1, %2};" : "=l"(r) : "f"(lo), "f"(hi)); return r;
}
__device__ __forceinline__ float2 unpk2(u64 v) {
    float2 f; asm("mov.b64 {%0, %1}, %2;" : "=f"(f.x), "=f"(f.y) : "l"(v)); return f;
}
__device__ __forceinline__ u64 ffma2(u64 a, u64 b, u64 c) {
    u64 d; asm("fma.rn.f32x2 %0, %1, %2, %3;" : "=l"(d) : "l"(a), "l"(b), "l"(c)); return d;
}
__device__ __forceinline__ u64 fadd2(u64 a, u64 b) {
    u64 d; asm("add.rn.f32x2 %0, %1, %2;" : "=l"(d) : "l"(a), "l"(b)); return d;
}

// ---------------------------------------------------------------------------
// qv GEMM: C[32r x 64c] = X[32 x 128] @ W[64 x 128]^T per CTA (R12 FFMA2
// inner loop; plain launch).
// ---------------------------------------------------------------------------
#define QV_SMEM_BYTES (32 * 128 * 4 + 128 * 68 * 4)

__global__ __launch_bounds__(128) void qv_kernel(const float* __restrict__ x,
                                                 const float* __restrict__ w_qkv) {
    extern __shared__ float sm[];
    float (*x_s)[128] = (float(*)[128])sm;
    float (*w_s)[68]  = (float(*)[68])(sm + 32 * 128);

    const int tid  = threadIdx.x;
    const int row0 = blockIdx.y * 32;
    const int st   = blockIdx.x;                           // 0,1 -> q ; 2,3 -> v
    const int wbase = (st < 2) ? st * 64 : 128 + st * 64;  // 0,64,256,320
    const float* w_rows = w_qkv + wbase * 128;

    {
        const float4* x4 = (const float4*)(x + row0 * 128);
        float4* xs4 = (float4*)x_s;
        #pragma unroll
        for (int i = 0; i < 8; i++) xs4[tid + i * 128] = x4[tid + i * 128];
    }
    #pragma unroll
    for (int i = 0; i < 64; i++) {
        int idx = tid + i * 128;
        int j = idx & 127, c = idx >> 7;
        w_s[j][c] = w_rows[c * 128 + j];
    }
    __syncthreads();

    const int tx = tid & 15;
    const int ty = tid >> 4;
    u64 acc2[4][2];
    #pragma unroll
    for (int r = 0; r < 4; r++) { acc2[r][0] = 0ULL; acc2[r][1] = 0ULL; }

    #pragma unroll 4
    for (int jb = 0; jb < 32; jb++) {
        float4 xr[4], wv[4];
        #pragma unroll
        for (int r = 0; r < 4; r++) xr[r] = *(const float4*)&x_s[ty * 4 + r][jb * 4];
        #pragma unroll
        for (int k = 0; k < 4; k++) wv[k] = *(const float4*)&w_s[jb * 4 + k][tx * 4];
        #pragma unroll
        for (int k = 0; k < 4; k++) {
            const u64 w01 = pack2(wv[k].x, wv[k].y);
            const u64 w23 = pack2(wv[k].z, wv[k].w);
            #pragma unroll
            for (int r = 0; r < 4; r++) {
                float xs = (k == 0) ? xr[r].x : (k == 1) ? xr[r].y
                         : (k == 2) ? xr[r].z : xr[r].w;
                const u64 x2 = pack2(xs, xs);
                acc2[r][0] = ffma2(x2, w01, acc2[r][0]);
                acc2[r][1] = ffma2(x2, w23, acc2[r][1]);
            }
        }
    }

    const float scale = (st < 2) ? 0.25f : 1.0f;
    float* dst = (st < 2) ? g_q : g_v;
    const int cg = (st & 1) * 64 + tx * 4;
    #pragma unroll
    for (int r = 0; r < 4; r++) {
        float2 a01 = unpk2(acc2[r][0]);
        float2 a23 = unpk2(acc2[r][1]);
        float4 o = {a01.x * scale, a01.y * scale, a23.x * scale, a23.y * scale};
        *(float4*)&dst[(row0 + ty * 4 + r) * 128 + cg] = o;
    }
}

// ---------------------------------------------------------------------------
// Attention + projection with ACTIVE-DIMENSION FOLDING.
// For each d: root r=-b/w of (em*w+b). If r outside (0,1) ("inactive"),
// lrelu is affine on [0,1) -> folds into constants (zero m-loop work).
// Active d's (~half, fixed per head): m-packed registers em2[8] hold all 16
// m values; loop d-outer over the warp-uniform active bitmask.
//   phase1: s_m = c0 + c1*em + sum_{active d} g_d |em + r_d|
//   phase2: hat_d inactive: v + (sl*S1 + ic*Z)/Z
//           hat_d active:   v + (0.505(w S1 + b Z) + 0.495|w| A_d)/Z,
//           A_d = sum_m p|em + r_d|  (d-outer m-packed loop)
// ---------------------------------------------------------------------------
__global__ __launch_bounds__(256, 3) void attn_proj_kernel(const float* __restrict__ e,
                                                           const float* __restrict__ w_ekv,
                                                           const float* __restrict__ b_ekv,
                                                           const float* __restrict__ w_prj,
                                                           const float* __restrict__ b_prj,
                                                           float* __restrict__ out) {
    __shared__ float e_s[N_];
    __shared__ float q_s[128], v_s[128];
    __shared__ float wk_s[128], bk_s[128], wv_s[128], bv_s[128];
    __shared__ float hat_s[128];

    const int row  = blockIdx.x;     // b*N + n
    const int tid  = threadIdx.x;
    const int lane = tid & 31;
    const int h    = tid >> 5;       // warp == head

    if (tid < 128)
        ((float4*)e_s)[tid] = ((const float4*)(e + row * N_))[tid];
    if (tid < 128) {
        q_s[tid]  = g_q[row * 128 + tid];
        v_s[tid]  = g_v[row * 128 + tid];
        wk_s[tid] = w_ekv[tid];
        bk_s[tid] = b_ekv[tid];
    } else {
        int t = tid - 128;
        wv_s[t] = w_ekv[128 + t];
        bv_s[t] = b_ekv[128 + t];
    }
    __syncthreads();

    // ---- all 16 m values of this lane, packed as 8 (m, m+256) pairs ----
    u64 em2[8];
    #pragma unroll
    for (int i = 0; i < 8; i++)
        em2[i] = pack2(e_s[i * 32 + lane], e_s[i * 32 + 256 + lane]);

    // ======== K-side classification (lane<16 owns d=lane) ========
    float wK = 0.f, bK = 0.f, qd = 0.f;
    if (lane < 16) {
        wK = wk_s[h * 16 + lane];
        bK = bk_s[h * 16 + lane];
        qd = q_s[h * 16 + lane];
    }
    float rK = __fdividef(bK, wK);          // lane>=16: nan -> inactive
    bool actK = (rK > -1.f) && (rK < 0.f);  // root -r in (0,1)
    float gK = 0.495f * qd * fabsf(wK);
    float c1 , c0;
    if (actK) { c1 = 0.505f * qd * wK; c0 = 0.505f * qd * bK; }
    else {
        bool pos = (fmaf(0.5f, wK, bK) > 0.f);   // constant-sign branch
        c1 = qd * (pos ? wK : 0.01f * wK);
        c0 = qd * (pos ? bK : 0.01f * bK);
    }
    #pragma unroll
    for (int k = 16; k >= 1; k >>= 1) {
        c1 += __shfl_xor_sync(FULLM, c1, k);
        c0 += __shfl_xor_sync(FULLM, c0, k);
    }
    const unsigned mK = __ballot_sync(FULLM, actK);

    // ======== phase 1: d-outer over active K dims ========
    u64 s2[8];
    #pragma unroll
    for (int i = 0; i < 8; i++) s2[i] = 0ULL;
    for (unsigned mm = mK; mm; mm &= (mm - 1)) {
        int d = __ffs(mm) - 1;
        float r = __shfl_sync(FULLM, rK, d);
        float g = __shfl_sync(FULLM, gK, d);
        u64 r2 = pack2(r, r);
        u64 g2 = pack2(g, g);
        #pragma unroll
        for (int i = 0; i < 8; i++)
            s2[i] = ffma2(g2, fadd2(em2[i], r2) & ABS2_MASK, s2[i]);
    }
    float s[16];
    #pragma unroll
    for (int i = 0; i < 8; i++) {
        float2 f  = unpk2(s2[i]);
        float2 ee = unpk2(em2[i]);
        s[i]     = fmaf(c1, ee.x, c0) + f.x;
        s[i + 8] = fmaf(c1, ee.y, c0) + f.y;
    }

    // ======== softmax over m (+ S1 = sum p*em) ========
    float mx = s[0];
    #pragma unroll
    for (int i = 1; i < 16; i++) mx = fmaxf(mx, s[i]);
    #pragma unroll
    for (int k = 16; k >= 1; k >>= 1) mx = fmaxf(mx, __shfl_xor_sync(FULLM, mx, k));
    float Z = 0.f, S1 = 0.f;
    #pragma unroll
    for (int i = 0; i < 8; i++) {
        float2 ee = unpk2(em2[i]);
        float pa = __expf(s[i] - mx);
        float pb = __expf(s[i + 8] - mx);
        Z += pa + pb;
        S1 = fmaf(pa, ee.x, fmaf(pb, ee.y, S1));
        s[i] = pa; s[i + 8] = pb;
    }
    #pragma unroll
    for (int k = 16; k >= 1; k >>= 1) {
        Z  += __shfl_xor_sync(FULLM, Z, k);
        S1 += __shfl_xor_sync(FULLM, S1, k);
    }
    const float invZ = 1.f / Z;

    u64 p2[8];
    #pragma unroll
    for (int i = 0; i < 8; i++) p2[i] = pack2(s[i], s[i + 8]);

    // ======== V-side classification ========
    float wV = 0.f, bV = 0.f, vD = 0.f;
    if (lane < 16) {
        wV = wv_s[h * 16 + lane];
        bV = bv_s[h * 16 + lane];
        vD = v_s[h * 16 + lane];
    }
    float rV = __fdividef(bV, wV);
    bool actV = (rV > -1.f) && (rV < 0.f);
    const unsigned mV = __ballot_sync(FULLM, actV);

    // ======== phase 2: d-outer over active V dims ========
    float A_own = 0.f;
    for (unsigned mm = mV; mm; mm &= (mm - 1)) {
        int d = __ffs(mm) - 1;
        float r = __shfl_sync(FULLM, rV, d);
        u64 r2 = pack2(r, r);
        u64 a2 = 0ULL;
        #pragma unroll
        for (int i = 0; i < 8; i++)
            a2 = ffma2(p2[i], fadd2(em2[i], r2) & ABS2_MASK, a2);
        float2 f = unpk2(a2);
        float A = f.x + f.y;
        #pragma unroll
        for (int k = 16; k >= 1; k >>= 1) A += __shfl_xor_sync(FULLM, A, k);
        if (lane == d) A_own = A;
    }

    // ======== epilogue: hat ========
    if (lane < 16) {
        float hat;
        if (actV) {
            hat = vD + (0.505f * fmaf(wV, S1, bV * Z)
                        + 0.495f * fabsf(wV) * A_own) * invZ;
        } else {
            bool pos = (fmaf(0.5f, wV, bV) > 0.f);
            float sl = pos ? wV : 0.01f * wV;
            float ic = pos ? bV : 0.01f * bV;
            hat = vD + fmaf(sl, S1, ic * Z) * invZ;
        }
        hat_s[h * 16 + lane] = hat;
    }
    __syncthreads();

    // ======== projection: warp h -> cols [h*16, h*16+16) ========
    {
        float4 h4 = ((const float4*)hat_s)[lane];
        float pc[16];
        #pragma unroll
        for (int i = 0; i < 16; i++) {
            const int c = h * 16 + i;
            float4 wv = *(const float4*)&w_prj[c * 128 + lane * 4];
            pc[i] = fmaf(h4.x, wv.x, fmaf(h4.y, wv.y, fmaf(h4.z, wv.z, h4.w * wv.w)));
        }
        #pragma unroll
        for (int r = 0; r < 4; r++) {
            const int half = 8 >> r;
            const bool hi = (lane >> r) & 1;
            #pragma unroll
            for (int j = 0; j < 8; j++) {
                if (j < half) {
                    float send = hi ? pc[j] : pc[j + half];
                    float keep = hi ? pc[j + half] : pc[j];
                    float recv = __shfl_xor_sync(FULLM, send, 1 << r);
                    pc[j] = keep + recv;
                }
            }
        }
        float cval = pc[0] + __shfl_xor_sync(FULLM, pc[0], 16);
        if (lane < 16) {
            int i = ((lane & 1) << 3) | (((lane >> 1) & 1) << 2)
                  | (((lane >> 2) & 1) << 1) | ((lane >> 3) & 1);
            const int c = h * 16 + i;
            out[row * 128 + c] = cval + b_prj[c];
        }
    }
}

// ---------------------------------------------------------------------------
extern "C" void kernel_launch(void* const* d_in, const int* in_sizes, int n_in,
                              void* d_out, int out_size) {
    const float* x     = (const float*)d_in[0];
    const float* e     = (const float*)d_in[1];
    const float* w_qkv = (const float*)d_in[2];
    const float* w_ekv = (const float*)d_in[3];
    const float* b_ekv = (const float*)d_in[4];
    const float* w_prj = (const float*)d_in[5];
    const float* b_prj = (const float*)d_in[6];
    float* out = (float*)d_out;

    cudaFuncSetAttribute((const void*)qv_kernel,
                         cudaFuncAttributeMaxDynamicSharedMemorySize, QV_SMEM_BYTES);

    qv_kernel       <<<dim3(4, 32), 128, QV_SMEM_BYTES>>>(x, w_qkv);
    attn_proj_kernel<<<ROWS_,       256>>>(e, w_ekv, b_ekv, w_prj, b_prj, out);
}